// round 10
// baseline (speedup 1.0000x reference)
#include <cuda_runtime.h>
#include <cuda_fp16.h>
#include <cstdint>

// Problem constants
#define NB    32
#define CIN   128
#define HH    112
#define WW    112
#define COUT  256
#define TH    8
#define TW    16

// SMEM layout (dynamic)
#define A_TILE   16384              // 128 oc x 64 c fp16, SW128-swizzled
#define NBUF     2                  // A-tile ring depth
#define P_CELL   144                // bytes per (y,x) cell: 64ch*2B + 16B pad
#define P_BYTES  (180 * P_CELL)     // 10*18 cells = 25920 B
#define S_P0     (NBUF * A_TILE)    // 32768
#define S_P1     (S_P0 + P_BYTES)   // 58688
#define S_TOTAL  (S_P1 + P_BYTES)   // 84608 -> 2 CTAs/SM

// Pre-rounded fp16 weights: [ocg(2)][cblk(2)][tap(9)] 16KB tiles, SW128-swizzled
__device__ unsigned char g_wA[2 * 2 * 9 * A_TILE];   // 576 KB

// ---------------------------------------------------------------------------
// Helpers
// ---------------------------------------------------------------------------
__device__ __forceinline__ uint32_t swz128(uint32_t off) {
    return off ^ ((off >> 3) & 0x70);
}
__device__ __forceinline__ uint32_t smem_u32(const void* p) {
    uint32_t a;
    asm("{ .reg .u64 t; cvta.to.shared.u64 t, %1; cvt.u32.u64 %0, t; }"
        : "=r"(a) : "l"(p));
    return a;
}
__device__ __forceinline__ void ldsm4(uint32_t* r, uint32_t addr) {
    asm volatile("ldmatrix.sync.aligned.m8n8.x4.shared.b16 {%0,%1,%2,%3}, [%4];"
                 : "=r"(r[0]), "=r"(r[1]), "=r"(r[2]), "=r"(r[3]) : "r"(addr));
}
__device__ __forceinline__ void mma16816(float* d, const uint32_t* a,
                                         const uint32_t* b) {
    asm volatile(
        "mma.sync.aligned.m16n8k16.row.col.f32.f16.f16.f32 "
        "{%0,%1,%2,%3}, {%4,%5,%6,%7}, {%8,%9}, {%0,%1,%2,%3};"
        : "+f"(d[0]), "+f"(d[1]), "+f"(d[2]), "+f"(d[3])
        : "r"(a[0]), "r"(a[1]), "r"(a[2]), "r"(a[3]), "r"(b[0]), "r"(b[1]));
}
__device__ __forceinline__ void cpasync16(uint32_t dst, const void* src) {
    asm volatile("cp.async.cg.shared.global [%0], [%1], 16;"
                 :: "r"(dst), "l"(src) : "memory");
}

// ---------------------------------------------------------------------------
// Kernel 1: round weights to fp16 tiles [ocg][cblk][tap], SW128-swizzled.
// ---------------------------------------------------------------------------
__global__ void wprep_kernel(const float* __restrict__ w) {
    int j = blockIdx.x * blockDim.x + threadIdx.x;   // 256 oc * 9 tap * 64 cpair
    if (j >= 256 * 9 * 64) return;
    int cpair = j & 63;
    int tap   = (j >> 6) % 9;
    int oc    = j / 576;
    int c     = cpair * 2;
    int ocg   = oc >> 7, ocl = oc & 127;
    int cblk  = c >> 6,  cl  = c & 63;

    __half h0 = __float2half_rn(w[((size_t)oc * CIN + c) * 9 + tap]);
    __half h1 = __float2half_rn(w[((size_t)oc * CIN + c + 1) * 9 + tap]);
    uint32_t hi = (uint32_t)__half_as_ushort(h0) |
                  ((uint32_t)__half_as_ushort(h1) << 16);

    size_t base = (size_t)(((ocg * 2 + cblk) * 9 + tap)) * A_TILE;
    uint32_t off = swz128((uint32_t)(ocl * 128 + cl * 2));
    *(uint32_t*)(g_wA + base + off) = hi;
}

// ---------------------------------------------------------------------------
// Kernel 2: implicit-GEMM conv, single-stream fp16 MMA.
// 4 warps, warp tile 64x64 (halves A-fragment LDSM replication -> smem
// crossbar 192KB->128KB per tap per SM). Patch double-buffered (cblk1 built
// under cblk0's MMAs), A-tile ring depth 2.
// grid = (98, 32, 2), block = 128, 2 CTAs/SM
// ---------------------------------------------------------------------------
extern __shared__ unsigned char smem[];

__global__ __launch_bounds__(128, 2)
void conv_mma_kernel(const float* __restrict__ in,
                     const float* __restrict__ bias,
                     float* __restrict__ out) {
    const int tid = threadIdx.x;
    const int wid = tid >> 5;
    const int lid = tid & 31;
    const int wm  = wid & 1;           // M half (64 oc)
    const int wn  = wid >> 1;          // N half (64 px)

    const int n   = blockIdx.y;
    const int ocg = blockIdx.z;
    const int h0  = (blockIdx.x / 7) * TH;
    const int w0  = (blockIdx.x % 7) * TW;

    const uint32_t sb = smem_u32(smem);

    // ---- accumulators, bias-initialized: acc[mt(4)][nt(8)][4] ----
    float acc[4][8][4];
    {
        const int r0 = lid >> 2;
#pragma unroll
        for (int mt = 0; mt < 4; ++mt) {
            const int oc0 = ocg * 128 + wm * 64 + mt * 16 + r0;
            const float b0 = __ldg(&bias[oc0]);
            const float b1 = __ldg(&bias[oc0 + 8]);
#pragma unroll
            for (int nt = 0; nt < 8; ++nt) {
                acc[mt][nt][0] = b0; acc[mt][nt][1] = b0;
                acc[mt][nt][2] = b1; acc[mt][nt][3] = b1;
            }
        }
    }

    // ---- per-lane ldmatrix address components (validated R6-R9) ----
    const uint32_t a_row = (uint32_t)(wm * 64 + (lid & 15));
    const uint32_t a_col = (uint32_t)((lid >> 4) << 4);
    const int nb_n   = (lid & 7) + ((lid >> 4) << 3);
    const uint32_t khoff = (uint32_t)(((lid >> 3) & 1) * 16);
    uint32_t bc[4];
#pragma unroll
    for (int g = 0; g < 4; ++g) {
        const int px = wn * 64 + g * 16 + nb_n;
        bc[g] = (uint32_t)(((px >> 4) * 18 + (px & 15)) * P_CELL) + khoff;
    }

    const float* inb = in + (size_t)n * CIN * HH * WW;

    auto ld_elem = [&](int i, int cb) -> float {
        const int c = i / 180;
        const int r = i - c * 180;
        const int y = r / 18;
        const int x = r - y * 18;
        const int gy = h0 - 1 + y;
        const int gx = w0 - 1 + x;
        float v = 0.0f;
        if (gy >= 0 && gy < HH && gx >= 0 && gx < WW)
            v = __ldg(&inb[((size_t)(cb * 64 + c) * HH + gy) * WW + gx]);
        return v;
    };
    auto cell_of = [&](int i) -> uint32_t {
        const int c = i / 180;
        const int r = i - c * 180;
        return (uint32_t)(r * P_CELL + c * 2);
    };

    // ---- A-tile prefetch (16KB per tap, 2-deep ring), 128 threads ----
    auto prefetchA = [&](int j) {
        const unsigned char* src =
            g_wA + (size_t)((ocg * 2 + (j / 9)) * 9 + (j % 9)) * A_TILE;
        const uint32_t dst = sb + (uint32_t)((j & 1) * A_TILE);
#pragma unroll
        for (int q = 0; q < 8; ++q)
            cpasync16(dst + tid * 16 + q * 2048, src + tid * 16 + q * 2048);
        asm volatile("cp.async.commit_group;" ::: "memory");
    };

    prefetchA(0);   // overlaps initial patch build

    // ---- initial patch build (cblk 0): 90 elements/thread ----
    for (int k = 0; k < 90; ++k) {
        const int i = tid + k * 128;
        const float v = ld_elem(i, 0);
        *(__half*)(smem + S_P0 + cell_of(i)) = __float2half_rn(v);
    }

    for (int cblk = 0; cblk < 2; ++cblk) {
        const uint32_t pbase = sb + (cblk == 0 ? S_P0 : S_P1);

        for (int tap = 0; tap < 9; ++tap) {
            const int j = cblk * 9 + tap;

            // ---- early LDGs for next cblk's patch (hidden under this tap) ----
            float pv[10];
            if (cblk == 0) {
#pragma unroll
                for (int q = 0; q < 10; ++q)
                    pv[q] = ld_elem(tid + (tap * 10 + q) * 128, 1);
            }

            // wait for A[j] (copied under tap j-1), sync, prefetch A[j+1]
            asm volatile("cp.async.wait_group 0;" ::: "memory");
            __syncthreads();   // A[j] visible; buf (j-1)&1 released;
                               // tap0: also orders patch writes
            if (j < 17) prefetchA(j + 1);

            const uint32_t abuf = sb + (uint32_t)((j & 1) * A_TILE);
            const int kh = tap / 3, kw = tap - kh * 3;
            const uint32_t toff = (uint32_t)((kh * 18 + kw) * P_CELL);
            const uint32_t b_base = pbase + toff;

#pragma unroll
            for (int k16 = 0; k16 < 4; ++k16) {
                const uint32_t kb = (uint32_t)(k16 * 32);

                uint32_t af[4][4];
#pragma unroll
                for (int mt = 0; mt < 4; ++mt)
                    ldsm4(af[mt], abuf +
                          swz128((a_row + mt * 16) * 128 + kb + a_col));

                uint32_t bf[16];
#pragma unroll
                for (int g = 0; g < 4; ++g)
                    ldsm4(bf + g * 4, b_base + bc[g] + kb);

#pragma unroll
                for (int mt = 0; mt < 4; ++mt)
#pragma unroll
                    for (int nt = 0; nt < 8; ++nt)
                        mma16816(acc[mt][nt], af[mt], bf + nt * 2);
            }

            // ---- store next-cblk patch elements (LDG latency absorbed) ----
            if (cblk == 0) {
#pragma unroll
                for (int q = 0; q < 10; ++q) {
                    const int i = tid + (tap * 10 + q) * 128;
                    *(__half*)(smem + S_P1 + cell_of(i)) = __float2half_rn(pv[q]);
                }
            }
        }
    }

    // ---- epilogue: direct register -> global stores ----
    {
        const int r0 = lid >> 2;
        const int cp = (lid & 3) * 2;
#pragma unroll
        for (int mt = 0; mt < 4; ++mt) {
            const int oc0 = ocg * 128 + wm * 64 + mt * 16 + r0;
            float* ob0 = out + (((size_t)n * COUT + oc0) * HH + h0) * WW + w0;
            float* ob1 = ob0 + (size_t)8 * HH * WW;
#pragma unroll
            for (int nt = 0; nt < 8; ++nt) {
                const int px = wn * 64 + nt * 8 + cp;
                const int py = px >> 4;
                const int pw = px & 15;
                const size_t o = (size_t)py * WW + pw;
                *(float2*)(ob0 + o) = make_float2(acc[mt][nt][0], acc[mt][nt][1]);
                *(float2*)(ob1 + o) = make_float2(acc[mt][nt][2], acc[mt][nt][3]);
            }
        }
    }
}

// ---------------------------------------------------------------------------
// Launch
// ---------------------------------------------------------------------------
extern "C" void kernel_launch(void* const* d_in, const int* in_sizes, int n_in,
                              void* d_out, int out_size) {
    const float* input  = (const float*)d_in[0];   // (32,128,112,112)
    const float* weight = (const float*)d_in[1];   // (256,128,3,3)
    const float* bias   = (const float*)d_in[2];   // (256,)
    float* out = (float*)d_out;                    // (32,256,112,112)

    static bool configured = false;
    if (!configured) {
        cudaFuncSetAttribute(conv_mma_kernel,
                             cudaFuncAttributeMaxDynamicSharedMemorySize,
                             S_TOTAL);
        configured = true;
    }

    wprep_kernel<<<(256 * 9 * 64 + 255) / 256, 256>>>(weight);

    dim3 grid(14 * 7, NB, 2);
    conv_mma_kernel<<<grid, 128, S_TOTAL>>>(input, bias, out);
}

// round 11
// speedup vs baseline: 1.1598x; 1.1598x over previous
#include <cuda_runtime.h>
#include <cuda_fp16.h>
#include <cstdint>

// Problem constants
#define NB    32
#define CIN   128
#define HH    112
#define WW    112
#define COUT  256
#define TH    4            // output rows per CTA
#define TW    16           // output cols per CTA

// SMEM layout (dynamic)
#define A_TILE   16384              // 128 oc x 64 c fp16, SW128-swizzled
#define NBUF     2                  // A-tile ring depth
#define P_CELL   144                // bytes per (y,x) cell: 64ch*2B + 16B pad
#define P_ROWS   6                  // 4 + 2 halo
#define P_COLS   18                 // 16 + 2 halo
#define P_CELLS  (P_ROWS * P_COLS)  // 108
#define P_BYTES  (P_CELLS * P_CELL) // 15552
#define S_P0     (NBUF * A_TILE)    // 32768
#define S_P1     (S_P0 + P_BYTES)   // 48320
#define S_TOTAL  (S_P1 + P_BYTES)   // 63872 -> 3 CTAs/SM

// Pre-rounded fp16 weights: [ocg(2)][cblk(2)][tap(9)] 16KB tiles, SW128-swizzled
__device__ unsigned char g_wA[2 * 2 * 9 * A_TILE];   // 576 KB

// ---------------------------------------------------------------------------
// Helpers
// ---------------------------------------------------------------------------
__device__ __forceinline__ uint32_t swz128(uint32_t off) {
    return off ^ ((off >> 3) & 0x70);
}
__device__ __forceinline__ uint32_t smem_u32(const void* p) {
    uint32_t a;
    asm("{ .reg .u64 t; cvta.to.shared.u64 t, %1; cvt.u32.u64 %0, t; }"
        : "=r"(a) : "l"(p));
    return a;
}
__device__ __forceinline__ void ldsm4(uint32_t* r, uint32_t addr) {
    asm volatile("ldmatrix.sync.aligned.m8n8.x4.shared.b16 {%0,%1,%2,%3}, [%4];"
                 : "=r"(r[0]), "=r"(r[1]), "=r"(r[2]), "=r"(r[3]) : "r"(addr));
}
__device__ __forceinline__ void mma16816(float* d, const uint32_t* a,
                                         const uint32_t* b) {
    asm volatile(
        "mma.sync.aligned.m16n8k16.row.col.f32.f16.f16.f32 "
        "{%0,%1,%2,%3}, {%4,%5,%6,%7}, {%8,%9}, {%0,%1,%2,%3};"
        : "+f"(d[0]), "+f"(d[1]), "+f"(d[2]), "+f"(d[3])
        : "r"(a[0]), "r"(a[1]), "r"(a[2]), "r"(a[3]), "r"(b[0]), "r"(b[1]));
}
__device__ __forceinline__ void cpasync16(uint32_t dst, const void* src) {
    asm volatile("cp.async.cg.shared.global [%0], [%1], 16;"
                 :: "r"(dst), "l"(src) : "memory");
}

// ---------------------------------------------------------------------------
// Kernel 1: round weights to fp16 tiles [ocg][cblk][tap], SW128-swizzled.
// (unchanged from R7-R10, validated)
// ---------------------------------------------------------------------------
__global__ void wprep_kernel(const float* __restrict__ w) {
    int j = blockIdx.x * blockDim.x + threadIdx.x;   // 256 oc * 9 tap * 64 cpair
    if (j >= 256 * 9 * 64) return;
    int cpair = j & 63;
    int tap   = (j >> 6) % 9;
    int oc    = j / 576;
    int c     = cpair * 2;
    int ocg   = oc >> 7, ocl = oc & 127;
    int cblk  = c >> 6,  cl  = c & 63;

    __half h0 = __float2half_rn(w[((size_t)oc * CIN + c) * 9 + tap]);
    __half h1 = __float2half_rn(w[((size_t)oc * CIN + c + 1) * 9 + tap]);
    uint32_t hi = (uint32_t)__half_as_ushort(h0) |
                  ((uint32_t)__half_as_ushort(h1) << 16);

    size_t base = (size_t)(((ocg * 2 + cblk) * 9 + tap)) * A_TILE;
    uint32_t off = swz128((uint32_t)(ocl * 128 + cl * 2));
    *(uint32_t*)(g_wA + base + off) = hi;
}

// ---------------------------------------------------------------------------
// Kernel 2: implicit-GEMM conv, single-stream fp16 MMA.
// CTA = 128oc x 64px (4h x 16w), 4 warps (2M x 2N), warp tile 64x32.
// 3 CTAs/SM: reg ceiling 170 (scheduling slack), 3 desynchronized barrier
// domains per SMSP. A ring depth 2, patch double-buffered (cblk1 built
// under cblk0's MMAs with incremental index counters — no div/mod).
// grid = (196, 32, 2), block = 128
// ---------------------------------------------------------------------------
extern __shared__ unsigned char smem[];

__global__ __launch_bounds__(128, 3)
void conv_mma_kernel(const float* __restrict__ in,
                     const float* __restrict__ bias,
                     float* __restrict__ out) {
    const int tid = threadIdx.x;
    const int wid = tid >> 5;
    const int lid = tid & 31;
    const int wm  = wid & 1;           // M half (64 oc)
    const int wn  = wid >> 1;          // N half (32 px)

    const int n   = blockIdx.y;
    const int ocg = blockIdx.z;
    const int h0  = (blockIdx.x / 7) * TH;
    const int w0  = (blockIdx.x % 7) * TW;

    const uint32_t sb = smem_u32(smem);

    // ---- accumulators, bias-initialized ----
    float acc[4][4][4];
    {
        const int r0 = lid >> 2;
#pragma unroll
        for (int mt = 0; mt < 4; ++mt) {
            const int oc0 = ocg * 128 + wm * 64 + mt * 16 + r0;
            const float b0 = __ldg(&bias[oc0]);
            const float b1 = __ldg(&bias[oc0 + 8]);
#pragma unroll
            for (int nt = 0; nt < 4; ++nt) {
                acc[mt][nt][0] = b0; acc[mt][nt][1] = b0;
                acc[mt][nt][2] = b1; acc[mt][nt][3] = b1;
            }
        }
    }

    // ---- per-lane ldmatrix address components (validated R6-R10) ----
    const uint32_t a_row = (uint32_t)(wm * 64 + (lid & 15));
    const uint32_t a_col = (uint32_t)((lid >> 4) << 4);
    const int nb_n   = (lid & 7) + ((lid >> 4) << 3);
    const uint32_t khoff = (uint32_t)(((lid >> 3) & 1) * 16);
    const int px0 = wn * 32 + nb_n;          // 0..63
    const int px1 = px0 + 16;
    const uint32_t bc0 =
        (uint32_t)(((px0 >> 4) * P_COLS + (px0 & 15)) * P_CELL) + khoff;
    const uint32_t bc1 =
        (uint32_t)(((px1 >> 4) * P_COLS + (px1 & 15)) * P_CELL) + khoff;

    const float* inb = in + (size_t)n * CIN * HH * WW;

    // ---- incremental patch-build counters: element i = tid + k*128,
    //      i -> (c = i/108, y = (i%108)/18, x = i%18); stride 128 = (c+1, y+1, x+2)
    const int c_init = tid / 108;            // 0 or 1 (tid < 128)
    const int rr     = tid - c_init * 108;
    const int y_init = rr / 18;
    const int x_init = rr - y_init * 18;

    // load one patch element at counter state, for channel block cb
    auto ld_at = [&](int cc, int yy, int xx, int cb) -> float {
        const int gy = h0 - 1 + yy;
        const int gx = w0 - 1 + xx;
        float v = 0.0f;
        if (gy >= 0 && gy < HH && gx >= 0 && gx < WW)
            v = __ldg(&inb[((size_t)(cb * 64 + cc) * HH + gy) * WW + gx]);
        return v;
    };
    auto advance = [](int& cc, int& yy, int& xx) {
        cc += 1; yy += 1; xx += 2;
        if (xx >= 18) { xx -= 18; yy += 1; }
        if (yy >= 6)  { yy -= 6;  cc += 1; }
    };

    // ---- A-tile prefetch (16KB per tap, 2-deep ring), 128 threads ----
    auto prefetchA = [&](int j) {
        const unsigned char* src =
            g_wA + (size_t)((ocg * 2 + (j / 9)) * 9 + (j % 9)) * A_TILE;
        const uint32_t dst = sb + (uint32_t)((j & 1) * A_TILE);
#pragma unroll
        for (int q = 0; q < 8; ++q)
            cpasync16(dst + tid * 16 + q * 2048, src + tid * 16 + q * 2048);
        asm volatile("cp.async.commit_group;" ::: "memory");
    };

    prefetchA(0);   // overlaps initial patch build

    // ---- initial patch build (cblk 0): 54 elements/thread ----
    {
        int cc = c_init, yy = y_init, xx = x_init;
        for (int k = 0; k < 54; ++k) {
            const float v = ld_at(cc, yy, xx, 0);
            const uint32_t cell =
                (uint32_t)((yy * P_COLS + xx) * P_CELL + cc * 2);
            *(__half*)(smem + S_P0 + cell) = __float2half_rn(v);
            advance(cc, yy, xx);
        }
    }

    // hidden-build counters for cblk 1 (6 elements per tap x 9 taps = 54)
    int hc = c_init, hy = y_init, hx = x_init;

    for (int cblk = 0; cblk < 2; ++cblk) {
        const uint32_t pbase = sb + (cblk == 0 ? S_P0 : S_P1);

        for (int tap = 0; tap < 9; ++tap) {
            const int j = cblk * 9 + tap;

            // ---- early LDGs for next cblk's patch (hidden under this tap) ----
            float pv[6];
            uint32_t pcell[6];
            if (cblk == 0) {
#pragma unroll
                for (int q = 0; q < 6; ++q) {
                    pv[q] = ld_at(hc, hy, hx, 1);
                    pcell[q] = (uint32_t)((hy * P_COLS + hx) * P_CELL + hc * 2);
                    advance(hc, hy, hx);
                }
            }

            // wait for A[j] (copied under tap j-1), sync, prefetch A[j+1]
            asm volatile("cp.async.wait_group 0;" ::: "memory");
            __syncthreads();   // A[j] visible; buf (j-1)&1 released;
                               // tap0: also orders patch writes
            if (j < 17) prefetchA(j + 1);

            const uint32_t abuf = sb + (uint32_t)((j & 1) * A_TILE);
            const int kh = tap / 3, kw = tap - kh * 3;
            const uint32_t toff = (uint32_t)((kh * P_COLS + kw) * P_CELL);
            const uint32_t b_base = pbase + toff;

#pragma unroll
            for (int k16 = 0; k16 < 4; ++k16) {
                const uint32_t kb = (uint32_t)(k16 * 32);

                uint32_t af[4][4];
#pragma unroll
                for (int mt = 0; mt < 4; ++mt)
                    ldsm4(af[mt], abuf +
                          swz128((a_row + mt * 16) * 128 + kb + a_col));

                uint32_t bf[8];
                ldsm4(bf,     b_base + bc0 + kb);
                ldsm4(bf + 4, b_base + bc1 + kb);

#pragma unroll
                for (int mt = 0; mt < 4; ++mt)
#pragma unroll
                    for (int nt = 0; nt < 4; ++nt)
                        mma16816(acc[mt][nt], af[mt], bf + nt * 2);
            }

            // ---- store next-cblk patch elements (LDG latency absorbed) ----
            if (cblk == 0) {
#pragma unroll
                for (int q = 0; q < 6; ++q)
                    *(__half*)(smem + S_P1 + pcell[q]) = __float2half_rn(pv[q]);
            }
        }
    }

    // ---- epilogue: direct register -> global stores ----
    {
        const int r0 = lid >> 2;
        const int cp = (lid & 3) * 2;
#pragma unroll
        for (int mt = 0; mt < 4; ++mt) {
            const int oc0 = ocg * 128 + wm * 64 + mt * 16 + r0;
            float* ob0 = out + (((size_t)n * COUT + oc0) * HH + h0) * WW + w0;
            float* ob1 = ob0 + (size_t)8 * HH * WW;
#pragma unroll
            for (int nt = 0; nt < 4; ++nt) {
                const int px = wn * 32 + nt * 8 + cp;   // 0..63
                const int py = px >> 4;                 // 0..3
                const int pw = px & 15;
                const size_t o = (size_t)py * WW + pw;
                *(float2*)(ob0 + o) = make_float2(acc[mt][nt][0], acc[mt][nt][1]);
                *(float2*)(ob1 + o) = make_float2(acc[mt][nt][2], acc[mt][nt][3]);
            }
        }
    }
}

// ---------------------------------------------------------------------------
// Launch
// ---------------------------------------------------------------------------
extern "C" void kernel_launch(void* const* d_in, const int* in_sizes, int n_in,
                              void* d_out, int out_size) {
    const float* input  = (const float*)d_in[0];   // (32,128,112,112)
    const float* weight = (const float*)d_in[1];   // (256,128,3,3)
    const float* bias   = (const float*)d_in[2];   // (256,)
    float* out = (float*)d_out;                    // (32,256,112,112)

    static bool configured = false;
    if (!configured) {
        cudaFuncSetAttribute(conv_mma_kernel,
                             cudaFuncAttributeMaxDynamicSharedMemorySize,
                             S_TOTAL);
        configured = true;
    }

    wprep_kernel<<<(256 * 9 * 64 + 255) / 256, 256>>>(weight);

    dim3 grid(28 * 7, NB, 2);   // 196 x 32 x 2
    conv_mma_kernel<<<grid, 128, S_TOTAL>>>(input, bias, out);
}

// round 12
// speedup vs baseline: 1.1994x; 1.0342x over previous
#include <cuda_runtime.h>
#include <cuda_fp16.h>
#include <cstdint>

// Problem constants
#define NB    32
#define CIN   128
#define HH    112
#define WW    112
#define COUT  256
#define TH    8
#define TW    16

// SMEM layout (dynamic)
#define A_TILE   16384              // 128 oc x 64 c fp16, SW128-swizzled
#define A_UNIT   (2 * A_TILE)       // full-K tap unit (c 0..127), 32KB
#define P_CELL   272                // bytes per (y,x) cell: 128ch*2B + 16B pad
#define P_COLS   18
#define P_ROWS   10
#define P_CELLS  (P_ROWS * P_COLS)  // 180
#define P_BYTES  (P_CELLS * P_CELL) // 48960
#define S_P      (2 * A_UNIT)       // 65536
#define S_TOTAL  (S_P + P_BYTES)    // 114496 -> 2 CTAs/SM

// Pre-rounded fp16 weights: [ocg(2)][tap(9)][chalf(2)] 16KB tiles, SW128-swizzled
__device__ unsigned char g_wA[2 * 9 * 2 * A_TILE];   // 576 KB

// ---------------------------------------------------------------------------
// Helpers
// ---------------------------------------------------------------------------
__device__ __forceinline__ uint32_t swz128(uint32_t off) {
    return off ^ ((off >> 3) & 0x70);
}
__device__ __forceinline__ uint32_t smem_u32(const void* p) {
    uint32_t a;
    asm("{ .reg .u64 t; cvta.to.shared.u64 t, %1; cvt.u32.u64 %0, t; }"
        : "=r"(a) : "l"(p));
    return a;
}
__device__ __forceinline__ void ldsm4(uint32_t* r, uint32_t addr) {
    asm volatile("ldmatrix.sync.aligned.m8n8.x4.shared.b16 {%0,%1,%2,%3}, [%4];"
                 : "=r"(r[0]), "=r"(r[1]), "=r"(r[2]), "=r"(r[3]) : "r"(addr));
}
__device__ __forceinline__ void mma16816(float* d, const uint32_t* a,
                                         const uint32_t* b) {
    asm volatile(
        "mma.sync.aligned.m16n8k16.row.col.f32.f16.f16.f32 "
        "{%0,%1,%2,%3}, {%4,%5,%6,%7}, {%8,%9}, {%0,%1,%2,%3};"
        : "+f"(d[0]), "+f"(d[1]), "+f"(d[2]), "+f"(d[3])
        : "r"(a[0]), "r"(a[1]), "r"(a[2]), "r"(a[3]), "r"(b[0]), "r"(b[1]));
}
__device__ __forceinline__ void cpasync16(uint32_t dst, const void* src) {
    asm volatile("cp.async.cg.shared.global [%0], [%1], 16;"
                 :: "r"(dst), "l"(src) : "memory");
}

// ---------------------------------------------------------------------------
// Kernel 1: round weights to fp16 tiles [ocg][tap][chalf], SW128-swizzled.
// (same tile internals as R7-R11, validated; only the tile ordering changed
//  so a full-K tap unit is one contiguous 32KB block)
// ---------------------------------------------------------------------------
__global__ void wprep_kernel(const float* __restrict__ w) {
    int j = blockIdx.x * blockDim.x + threadIdx.x;   // 256 oc * 9 tap * 64 cpair
    if (j >= 256 * 9 * 64) return;
    int cpair = j & 63;
    int tap   = (j >> 6) % 9;
    int oc    = j / 576;
    int c     = cpair * 2;
    int ocg   = oc >> 7, ocl = oc & 127;
    int chalf = c >> 6,  cl  = c & 63;

    __half h0 = __float2half_rn(w[((size_t)oc * CIN + c) * 9 + tap]);
    __half h1 = __float2half_rn(w[((size_t)oc * CIN + c + 1) * 9 + tap]);
    uint32_t hi = (uint32_t)__half_as_ushort(h0) |
                  ((uint32_t)__half_as_ushort(h1) << 16);

    size_t base = (size_t)(((ocg * 9 + tap) * 2 + chalf)) * A_TILE;
    uint32_t off = swz128((uint32_t)(ocl * 128 + cl * 2));
    *(uint32_t*)(g_wA + base + off) = hi;
}

// ---------------------------------------------------------------------------
// Kernel 2: implicit-GEMM conv, single-stream fp16 MMA.
// Full K=128 per sync unit: single patch (built once), 9 sync units,
// 32KB A units double-buffered via cp.async.
// grid = (98, 32, 2), block = 256, 2 CTAs/SM
// ---------------------------------------------------------------------------
extern __shared__ unsigned char smem[];

__global__ __launch_bounds__(256, 2)
void conv_mma_kernel(const float* __restrict__ in,
                     const float* __restrict__ bias,
                     float* __restrict__ out) {
    const int tid = threadIdx.x;
    const int wid = tid >> 5;
    const int lid = tid & 31;
    const int wm  = wid & 1;           // M half (64 oc)
    const int wn  = wid >> 1;          // N quarter (32 px)

    const int n   = blockIdx.y;
    const int ocg = blockIdx.z;
    const int h0  = (blockIdx.x / 7) * TH;
    const int w0  = (blockIdx.x % 7) * TW;

    const uint32_t sb = smem_u32(smem);

    // ---- accumulators, bias-initialized ----
    float acc[4][4][4];
    {
        const int r0 = lid >> 2;
#pragma unroll
        for (int mt = 0; mt < 4; ++mt) {
            const int oc0 = ocg * 128 + wm * 64 + mt * 16 + r0;
            const float b0 = __ldg(&bias[oc0]);
            const float b1 = __ldg(&bias[oc0 + 8]);
#pragma unroll
            for (int nt = 0; nt < 4; ++nt) {
                acc[mt][nt][0] = b0; acc[mt][nt][1] = b0;
                acc[mt][nt][2] = b1; acc[mt][nt][3] = b1;
            }
        }
    }

    // ---- per-lane ldmatrix address components (validated R6-R11) ----
    const uint32_t a_row = (uint32_t)(wm * 64 + (lid & 15));
    const uint32_t a_col = (uint32_t)((lid >> 4) << 4);
    const int nb_n   = (lid & 7) + ((lid >> 4) << 3);
    const uint32_t khoff = (uint32_t)(((lid >> 3) & 1) * 16);
    const int px0 = wn * 32 + nb_n;
    const int px1 = px0 + 16;
    const uint32_t bc0 =
        (uint32_t)(((px0 >> 4) * P_COLS + (px0 & 15)) * P_CELL) + khoff;
    const uint32_t bc1 =
        (uint32_t)(((px1 >> 4) * P_COLS + (px1 & 15)) * P_CELL) + khoff;

    const float* inb = in + (size_t)n * CIN * HH * WW;

    // ---- A-unit prefetch (32KB per tap: both chalf tiles), 2-deep ring ----
    auto prefetchA = [&](int tap) {
        const unsigned char* src = g_wA + (size_t)(ocg * 9 + tap) * A_UNIT;
        const uint32_t dst = sb + (uint32_t)((tap & 1) * A_UNIT);
#pragma unroll
        for (int q = 0; q < 8; ++q)
            cpasync16(dst + tid * 16 + q * 4096, src + tid * 16 + q * 4096);
        asm volatile("cp.async.commit_group;" ::: "memory");
    };

    prefetchA(0);   // overlaps the patch build

    // ---- patch build (all 128 channels), 90 elements/thread,
    //      incremental (c,y,x) counters: i = tid + k*256, cell-major in i ----
    {
        int cc = tid / 180;
        int rm = tid - cc * 180;
        int yy = rm / 18;
        int xx = rm - yy * 18;
        for (int k = 0; k < 90; ++k) {
            const int gy = h0 - 1 + yy;
            const int gx = w0 - 1 + xx;
            float v = 0.0f;
            if (gy >= 0 && gy < HH && gx >= 0 && gx < WW)
                v = __ldg(&inb[((size_t)cc * HH + gy) * WW + gx]);
            const uint32_t cell =
                (uint32_t)((yy * P_COLS + xx) * P_CELL + cc * 2);
            *(__half*)(smem + S_P + cell) = __float2half_rn(v);
            // advance by 256 = 1*180 + 76 (76 = 4*18 + 4)
            cc += 1; yy += 4; xx += 4;
            if (xx >= 18) { xx -= 18; yy += 1; }
            if (yy >= 10) { yy -= 10; cc += 1; }
        }
    }

    for (int tap = 0; tap < 9; ++tap) {
        // wait for A[tap] (copied under tap-1), sync, prefetch A[tap+1]
        asm volatile("cp.async.wait_group 0;" ::: "memory");
        __syncthreads();   // A[tap] visible; buf (tap-1)&1 released;
                           // tap 0: also orders patch writes
        if (tap < 8) prefetchA(tap + 1);

        const uint32_t abase = sb + (uint32_t)((tap & 1) * A_UNIT);
        const int kh = tap / 3, kw = tap - kh * 3;
        const uint32_t b_base =
            sb + S_P + (uint32_t)((kh * P_COLS + kw) * P_CELL);

#pragma unroll
        for (int k16 = 0; k16 < 8; ++k16) {
            const uint32_t atile = abase + (uint32_t)((k16 >> 2) * A_TILE);
            const uint32_t kb = (uint32_t)((k16 & 3) * 32);

            uint32_t af[4][4];
#pragma unroll
            for (int mt = 0; mt < 4; ++mt)
                ldsm4(af[mt], atile +
                      swz128((a_row + mt * 16) * 128 + kb + a_col));

            uint32_t bf[8];
            const uint32_t bkb = (uint32_t)(k16 * 32);
            ldsm4(bf,     b_base + bc0 + bkb);
            ldsm4(bf + 4, b_base + bc1 + bkb);

#pragma unroll
            for (int mt = 0; mt < 4; ++mt)
#pragma unroll
                for (int nt = 0; nt < 4; ++nt)
                    mma16816(acc[mt][nt], af[mt], bf + nt * 2);
        }
    }

    // ---- epilogue: direct register -> global stores ----
    {
        const int r0 = lid >> 2;
        const int cp = (lid & 3) * 2;
#pragma unroll
        for (int mt = 0; mt < 4; ++mt) {
            const int oc0 = ocg * 128 + wm * 64 + mt * 16 + r0;
            float* ob0 = out + (((size_t)n * COUT + oc0) * HH + h0) * WW + w0;
            float* ob1 = ob0 + (size_t)8 * HH * WW;
#pragma unroll
            for (int nt = 0; nt < 4; ++nt) {
                const int px = wn * 32 + nt * 8 + cp;
                const int py = px >> 4;
                const int pw = px & 15;
                const size_t o = (size_t)py * WW + pw;
                *(float2*)(ob0 + o) = make_float2(acc[mt][nt][0], acc[mt][nt][1]);
                *(float2*)(ob1 + o) = make_float2(acc[mt][nt][2], acc[mt][nt][3]);
            }
        }
    }
}

// ---------------------------------------------------------------------------
// Launch
// ---------------------------------------------------------------------------
extern "C" void kernel_launch(void* const* d_in, const int* in_sizes, int n_in,
                              void* d_out, int out_size) {
    const float* input  = (const float*)d_in[0];   // (32,128,112,112)
    const float* weight = (const float*)d_in[1];   // (256,128,3,3)
    const float* bias   = (const float*)d_in[2];   // (256,)
    float* out = (float*)d_out;                    // (32,256,112,112)

    static bool configured = false;
    if (!configured) {
        cudaFuncSetAttribute(conv_mma_kernel,
                             cudaFuncAttributeMaxDynamicSharedMemorySize,
                             S_TOTAL);
        configured = true;
    }

    wprep_kernel<<<(256 * 9 * 64 + 255) / 256, 256>>>(weight);

    dim3 grid(14 * 7, NB, 2);   // 98 x 32 x 2
    conv_mma_kernel<<<grid, 256, S_TOTAL>>>(input, bias, out);
}